// round 9
// baseline (speedup 1.0000x reference)
#include <cuda_runtime.h>
#include <math_constants.h>

// CRF Viterbi decode, fused single kernel. Static smem (~41.9 KB).
//   X: [4096, 512, 128] f32   W: [26, 128] f32   T: [26, 26] f32
//   out: [4096, 512] labels, written as FLOAT32 values (0.0 .. 25.0).
//
// Emissions: 4 stride-4 partial sums via float4 (acc.x: k%4==0, ... acc.w)
// combined by adjacent pairwise reduction (x+y)+(z+w) -- the XLA dot-emitter
// SIMD pattern. R8 established serial-in-order FMA gives ~6 label flips;
// this tests the 4-partial order as the reference's true accumulation.

#define LSEQ   512
#define KLAB   26
#define DDIM   128
#define EPITCH 28          // e row pitch in floats (112 B, 16B-aligned)
#define WPITCH 132         // W row pitch in floats (528 B, 16B-aligned)
#define CHUNK  128
#define NCHUNK (LSEQ / CHUNK)
#define BATCH  4096

__global__ __launch_bounds__(128) void crf_viterbi_kernel(
    const float* __restrict__ X,
    const float* __restrict__ W,
    const float* __restrict__ T,
    float* __restrict__ out)
{
    __shared__ float e_sm[CHUNK * EPITCH];             // 14336 B
    __shared__ float w_sm[KLAB * WPITCH];              // 13728 B
    __shared__ unsigned char bp_sm[(LSEQ - 1) * KLAB]; // 13286 B
    __shared__ unsigned char lab[LSEQ];                //   512 B

    const int b    = blockIdx.x;
    const int tid  = threadIdx.x;
    const int warp = tid >> 5;
    const int lane = tid & 31;

    // ---- Stage W into smem ----
    for (int idx = tid; idx < KLAB * DDIM; idx += blockDim.x) {
        int k = idx >> 7;
        int d = idx & 127;
        w_sm[k * WPITCH + d] = W[idx];
    }

    // ---- Warp 0: preload T column T[j][lane] ----
    float Tcol[KLAB];
    if (warp == 0) {
        const int yy = lane < KLAB ? lane : 0;
        #pragma unroll
        for (int j = 0; j < KLAB; j++) Tcol[j] = T[j * KLAB + yy];
    }
    __syncthreads();

    const int kk = lane < KLAB ? lane : 0;
    const float4* w4 = reinterpret_cast<const float4*>(w_sm) + kk * (WPITCH / 4);

    float l = 0.0f;
    int y_last = 0;

    for (int c = 0; c < NCHUNK; c++) {
        // ---- Phase 1: emissions, 4 stride-4 partials + pairwise combine ----
        for (int i = warp; i < CHUNK; i += 4) {
            const int gi = c * CHUNK + i;
            const float4* x4 = reinterpret_cast<const float4*>(
                X + ((size_t)b * LSEQ + gi) * DDIM);
            float4 acc = make_float4(0.f, 0.f, 0.f, 0.f);
            #pragma unroll 8
            for (int q = 0; q < DDIM / 4; q++) {
                float4 xv = x4[q];
                float4 wv = w4[q];
                acc.x = fmaf(xv.x, wv.x, acc.x);   // partial over k % 4 == 0
                acc.y = fmaf(xv.y, wv.y, acc.y);   // k % 4 == 1
                acc.z = fmaf(xv.z, wv.z, acc.z);   // k % 4 == 2
                acc.w = fmaf(xv.w, wv.w, acc.w);   // k % 4 == 3
            }
            float e = (acc.x + acc.y) + (acc.z + acc.w);  // adjacent pairwise
            if (lane < KLAB) e_sm[i * EPITCH + lane] = e;
        }
        __syncthreads();

        // ---- Phase 2: warp 0 scans this chunk ----
        if (warp == 0) {
            const int t_end = (c == NCHUNK - 1) ? CHUNK - 1 : CHUNK;
            for (int i = 0; i < t_end; i++) {
                const int t = c * CHUNK + i;
                const float* er = e_sm + i * EPITCH;
                float ev[EPITCH];
                #pragma unroll
                for (int q = 0; q < EPITCH / 4; q++)
                    *reinterpret_cast<float4*>(ev + 4 * q) =
                        reinterpret_cast<const float4*>(er)[q];

                // Faithful association (e + T) + l; two strict-'>' chains keep
                // first occurrence; cross-chain tie -> lower index.
                float l0 = __shfl_sync(0xffffffffu, l, 0);
                float m0 = (ev[0] + Tcol[0]) + l0; int a0 = 0;
                float l1 = __shfl_sync(0xffffffffu, l, 1);
                float m1 = (ev[1] + Tcol[1]) + l1; int a1 = 1;
                #pragma unroll
                for (int j = 2; j < KLAB; j++) {
                    float lj = __shfl_sync(0xffffffffu, l, j);
                    float s  = (ev[j] + Tcol[j]) + lj;
                    if ((j & 1) == 0) { if (s > m0) { m0 = s; a0 = j; } }
                    else              { if (s > m1) { m1 = s; a1 = j; } }
                }
                float m; int am;
                if (m1 > m0 || (m1 == m0 && a1 < a0)) { m = m1; am = a1; }
                else                                  { m = m0; am = a0; }

                if (lane < KLAB) bp_sm[t * KLAB + lane] = (unsigned char)am;
                l = m;
            }

            if (c == NCHUNK - 1) {
                // Final scores + warp argmax (tie -> lowest index).
                float fs = (lane < KLAB)
                               ? (e_sm[(CHUNK - 1) * EPITCH + lane] + l)
                               : -CUDART_INF_F;
                int idx = lane;
                #pragma unroll
                for (int off = 16; off > 0; off >>= 1) {
                    float ov = __shfl_down_sync(0xffffffffu, fs, off);
                    int   oi = __shfl_down_sync(0xffffffffu, idx, off);
                    if (ov > fs || (ov == fs && oi < idx)) { fs = ov; idx = oi; }
                }
                y_last = __shfl_sync(0xffffffffu, idx, 0);

                // Backtrack (lane 0).
                if (lane == 0) {
                    int yv = y_last;
                    lab[LSEQ - 1] = (unsigned char)yv;
                    for (int t = LSEQ - 2; t >= 0; t--) {
                        yv = bp_sm[t * KLAB + yv];
                        lab[t] = (unsigned char)yv;
                    }
                }
            }
        }
        __syncthreads();
    }

    // ---- Phase 3: coalesced store, labels as float values ----
    float* orow = out + (size_t)b * LSEQ;
    for (int i = tid; i < LSEQ; i += blockDim.x)
        orow[i] = (float)lab[i];
}

extern "C" void kernel_launch(void* const* d_in, const int* in_sizes, int n_in,
                              void* d_out, int out_size)
{
    // Rank-resolve inputs: X largest, T smallest, W the remaining one.
    int ix = 0, it = 0;
    for (int i = 1; i < n_in && i < 3; i++) {
        if (in_sizes[i] > in_sizes[ix]) ix = i;
        if (in_sizes[i] < in_sizes[it]) it = i;
    }
    int iw = 3 - ix - it;
    if (n_in < 3 || iw < 0 || iw > 2 || ix == it) { ix = 0; iw = 1; it = 2; }

    const float* X = (const float*)d_in[ix];
    const float* W = (const float*)d_in[iw];
    const float* T = (const float*)d_in[it];
    float* out = (float*)d_out;
    (void)out_size;

    crf_viterbi_kernel<<<BATCH, 128>>>(X, W, T, out);
}

// round 10
// speedup vs baseline: 1.4097x; 1.4097x over previous
#include <cuda_runtime.h>
#include <math_constants.h>

// CRF Viterbi decode, fused single kernel. Static smem (~42 KB).
//   X: [4096, 512, 128] f32   W: [26, 128] f32   T: [26, 26] f32
//   out: [4096, 512] labels as FLOAT32 values (0.0 .. 25.0).
//
// R10 changes vs R9 (numerics frozen: identical per-row accumulation order):
//  - Phase 1 register-blocks R=4 rows/warp-iter: W LDS.128 count /4.
//  - Tcol loaded per-chunk inside phase 2 (frees phase-1 registers).
//  - Scan warp rotates per chunk (c & 3) with smem carry handoff, spreading
//    the serial scan across SMSPs instead of piling on SMSP0.

#define LSEQ   512
#define KLAB   26
#define DDIM   128
#define EPITCH 28          // e row pitch in floats (112 B, 16B-aligned)
#define WPITCH 132         // W row pitch in floats (528 B, 16B-aligned)
#define CHUNK  128
#define NCHUNK (LSEQ / CHUNK)
#define BATCH  4096
#define RBLK   4

__global__ __launch_bounds__(128) void crf_viterbi_kernel(
    const float* __restrict__ X,
    const float* __restrict__ W,
    const float* __restrict__ T,
    float* __restrict__ out)
{
    __shared__ float e_sm[CHUNK * EPITCH];             // 14336 B
    __shared__ float w_sm[KLAB * WPITCH];              // 13728 B
    __shared__ unsigned char bp_sm[(LSEQ - 1) * KLAB]; // 13286 B
    __shared__ unsigned char lab[LSEQ];                //   512 B
    __shared__ float carry_sm[32];                     //   128 B

    const int b    = blockIdx.x;
    const int tid  = threadIdx.x;
    const int warp = tid >> 5;
    const int lane = tid & 31;

    // ---- Stage W into smem ----
    for (int idx = tid; idx < KLAB * DDIM; idx += blockDim.x) {
        int k = idx >> 7;
        int d = idx & 127;
        w_sm[k * WPITCH + d] = W[idx];
    }
    __syncthreads();

    const int kk = lane < KLAB ? lane : 0;
    const float4* w4 = reinterpret_cast<const float4*>(w_sm) + kk * (WPITCH / 4);
    const int yy = lane < KLAB ? lane : 0;

    for (int c = 0; c < NCHUNK; c++) {
        // ---- Phase 1: emissions, R=4 rows per warp iteration ----
        // Per q: 1 W LDS.128 feeds 4 rows (16 FMA). Per-row accumulation
        // order is IDENTICAL to R9: float4 stride-4 partials, q = 0..31,
        // combined (x+y)+(z+w).
        for (int i0 = warp * RBLK; i0 < CHUNK; i0 += 4 * RBLK) {
            const int gi0 = c * CHUNK + i0;
            const float4* x0 = reinterpret_cast<const float4*>(
                X + ((size_t)b * LSEQ + gi0) * DDIM);
            const float4* x1 = x0 + (DDIM / 4);
            const float4* x2 = x1 + (DDIM / 4);
            const float4* x3 = x2 + (DDIM / 4);

            float4 a0 = make_float4(0.f, 0.f, 0.f, 0.f);
            float4 a1 = a0, a2 = a0, a3 = a0;

            #pragma unroll 8
            for (int q = 0; q < DDIM / 4; q++) {
                const float4 wv = w4[q];
                float4 xv;
                xv = x0[q];
                a0.x = fmaf(xv.x, wv.x, a0.x); a0.y = fmaf(xv.y, wv.y, a0.y);
                a0.z = fmaf(xv.z, wv.z, a0.z); a0.w = fmaf(xv.w, wv.w, a0.w);
                xv = x1[q];
                a1.x = fmaf(xv.x, wv.x, a1.x); a1.y = fmaf(xv.y, wv.y, a1.y);
                a1.z = fmaf(xv.z, wv.z, a1.z); a1.w = fmaf(xv.w, wv.w, a1.w);
                xv = x2[q];
                a2.x = fmaf(xv.x, wv.x, a2.x); a2.y = fmaf(xv.y, wv.y, a2.y);
                a2.z = fmaf(xv.z, wv.z, a2.z); a2.w = fmaf(xv.w, wv.w, a2.w);
                xv = x3[q];
                a3.x = fmaf(xv.x, wv.x, a3.x); a3.y = fmaf(xv.y, wv.y, a3.y);
                a3.z = fmaf(xv.z, wv.z, a3.z); a3.w = fmaf(xv.w, wv.w, a3.w);
            }
            if (lane < KLAB) {
                e_sm[(i0 + 0) * EPITCH + lane] = (a0.x + a0.y) + (a0.z + a0.w);
                e_sm[(i0 + 1) * EPITCH + lane] = (a1.x + a1.y) + (a1.z + a1.w);
                e_sm[(i0 + 2) * EPITCH + lane] = (a2.x + a2.y) + (a2.z + a2.w);
                e_sm[(i0 + 3) * EPITCH + lane] = (a3.x + a3.y) + (a3.z + a3.w);
            }
        }
        __syncthreads();

        // ---- Phase 2: scan this chunk; scanning warp rotates per chunk ----
        if (warp == (c & 3)) {
            float Tcol[KLAB];
            #pragma unroll
            for (int j = 0; j < KLAB; j++) Tcol[j] = T[j * KLAB + yy];

            float l = (c == 0) ? 0.0f : carry_sm[lane];

            const int t_end = (c == NCHUNK - 1) ? CHUNK - 1 : CHUNK;
            for (int i = 0; i < t_end; i++) {
                const int t = c * CHUNK + i;
                const float* er = e_sm + i * EPITCH;
                float ev[EPITCH];
                #pragma unroll
                for (int q = 0; q < EPITCH / 4; q++)
                    *reinterpret_cast<float4*>(ev + 4 * q) =
                        reinterpret_cast<const float4*>(er)[q];

                // Faithful association (e + T) + l; two strict-'>' chains keep
                // first occurrence; cross-chain tie -> lower index.
                float l0 = __shfl_sync(0xffffffffu, l, 0);
                float m0 = (ev[0] + Tcol[0]) + l0; int a0 = 0;
                float l1 = __shfl_sync(0xffffffffu, l, 1);
                float m1 = (ev[1] + Tcol[1]) + l1; int a1 = 1;
                #pragma unroll
                for (int j = 2; j < KLAB; j++) {
                    float lj = __shfl_sync(0xffffffffu, l, j);
                    float s  = (ev[j] + Tcol[j]) + lj;
                    if ((j & 1) == 0) { if (s > m0) { m0 = s; a0 = j; } }
                    else              { if (s > m1) { m1 = s; a1 = j; } }
                }
                float m; int am;
                if (m1 > m0 || (m1 == m0 && a1 < a0)) { m = m1; am = a1; }
                else                                  { m = m0; am = a0; }

                if (lane < KLAB) bp_sm[t * KLAB + lane] = (unsigned char)am;
                l = m;
            }

            if (c == NCHUNK - 1) {
                // Final scores + warp argmax (tie -> lowest index).
                float fs = (lane < KLAB)
                               ? (e_sm[(CHUNK - 1) * EPITCH + lane] + l)
                               : -CUDART_INF_F;
                int idx = lane;
                #pragma unroll
                for (int off = 16; off > 0; off >>= 1) {
                    float ov = __shfl_down_sync(0xffffffffu, fs, off);
                    int   oi = __shfl_down_sync(0xffffffffu, idx, off);
                    if (ov > fs || (ov == fs && oi < idx)) { fs = ov; idx = oi; }
                }
                int y_last = __shfl_sync(0xffffffffu, idx, 0);

                // Backtrack (lane 0 of the scanning warp).
                if (lane == 0) {
                    int yv = y_last;
                    lab[LSEQ - 1] = (unsigned char)yv;
                    for (int t = LSEQ - 2; t >= 0; t--) {
                        yv = bp_sm[t * KLAB + yv];
                        lab[t] = (unsigned char)yv;
                    }
                }
            } else {
                carry_sm[lane] = l;   // hand carry to next chunk's scan warp
            }
        }
        __syncthreads();
    }

    // ---- Phase 3: coalesced store, labels as float values ----
    float* orow = out + (size_t)b * LSEQ;
    for (int i = tid; i < LSEQ; i += blockDim.x)
        orow[i] = (float)lab[i];
}

extern "C" void kernel_launch(void* const* d_in, const int* in_sizes, int n_in,
                              void* d_out, int out_size)
{
    // Rank-resolve inputs: X largest, T smallest, W the remaining one.
    int ix = 0, it = 0;
    for (int i = 1; i < n_in && i < 3; i++) {
        if (in_sizes[i] > in_sizes[ix]) ix = i;
        if (in_sizes[i] < in_sizes[it]) it = i;
    }
    int iw = 3 - ix - it;
    if (n_in < 3 || iw < 0 || iw > 2 || ix == it) { ix = 0; iw = 1; it = 2; }

    const float* X = (const float*)d_in[ix];
    const float* W = (const float*)d_in[iw];
    const float* T = (const float*)d_in[it];
    float* out = (float*)d_out;
    (void)out_size;

    crf_viterbi_kernel<<<BATCH, 128>>>(X, W, T, out);
}

// round 12
// speedup vs baseline: 1.7846x; 1.2660x over previous
#include <cuda_runtime.h>
#include <math_constants.h>

// CRF Viterbi decode, fused single kernel. Static smem (~42 KB < 48 KB).
//   X: [4096, 512, 128] f32   W: [26, 128] f32   T: [26, 26] f32
//   out: [4096, 512] labels as FLOAT32 values (0.0 .. 25.0).
//
// R11 vs R10 (numerics bit-identical):
//  - X is STAGED through smem in 16-row tiles with fully coalesced LDG.128
//    (512 LDG.128/CTA instead of 16384 broadcast LDG.128), then read in
//    phase 1 as broadcast LDS.128. Kills the dominant L1/LSU consumer.
//  - Emission chunk shrinks 128 -> 64 rows to fit the X tile in static smem.
//  - Same RBLK=4 row blocking (W LDS count unchanged), same scan, same
//    accumulation order (stride-4 float4 partials, (x+y)+(z+w)).

#define LSEQ   512
#define KLAB   26
#define DDIM   128
#define EPITCH 28          // e row pitch in floats (112 B, 16B-aligned)
#define WPITCH 132         // W row pitch in floats (528 B, 16B-aligned)
#define CHUNK  64          // emission rows per scan chunk
#define NCHUNK (LSEQ / CHUNK)          // 8
#define TS     16          // X staging tile rows
#define NTILE  (CHUNK / TS)            // 4
#define RBLK   4           // rows per warp per tile (TS / 4 warps)
#define BATCH  4096

__global__ __launch_bounds__(128) void crf_viterbi_kernel(
    const float* __restrict__ X,
    const float* __restrict__ W,
    const float* __restrict__ T,
    float* __restrict__ out)
{
    __shared__ float e_sm[CHUNK * EPITCH];             //  7168 B
    __shared__ float w_sm[KLAB * WPITCH];              // 13728 B
    __shared__ float x_sm[TS * DDIM];                  //  8192 B
    __shared__ unsigned char bp_sm[(LSEQ - 1) * KLAB]; // 13286 B
    __shared__ unsigned char lab[LSEQ];                //   512 B
    __shared__ float carry_sm[32];                     //   128 B
                                                       // ~43.0 KB total

    const int b    = blockIdx.x;
    const int tid  = threadIdx.x;
    const int warp = tid >> 5;
    const int lane = tid & 31;

    // ---- Stage W into smem ----
    for (int idx = tid; idx < KLAB * DDIM; idx += blockDim.x) {
        int k = idx >> 7;
        int d = idx & 127;
        w_sm[k * WPITCH + d] = W[idx];
    }
    __syncthreads();

    const int kk = lane < KLAB ? lane : 0;
    const float4* w4 = reinterpret_cast<const float4*>(w_sm) + kk * (WPITCH / 4);
    const float4* xs4 = reinterpret_cast<const float4*>(x_sm);
    float4* xs4w = reinterpret_cast<float4*>(x_sm);
    const int yy = lane < KLAB ? lane : 0;

    for (int c = 0; c < NCHUNK; c++) {
        // ---- Phase 1: emissions for rows [c*CHUNK, (c+1)*CHUNK), staged ----
        for (int s = 0; s < NTILE; s++) {
            const int row0 = c * CHUNK + s * TS;     // global first row of tile

            // Stage TS x 128 floats coalesced: 512 float4, 4 per thread.
            {
                const float4* xg = reinterpret_cast<const float4*>(
                    X + ((size_t)b * LSEQ + row0) * DDIM);
                #pragma unroll
                for (int u = 0; u < (TS * DDIM / 4) / 128; u++)
                    xs4w[tid + u * 128] = xg[tid + u * 128];
            }
            __syncthreads();

            // Compute RBLK=4 rows per warp from x_sm (broadcast LDS.128).
            // Per-row accumulation order IDENTICAL to R9/R10.
            {
                const int lr0 = warp * RBLK;          // local row in tile
                const float4* x0 = xs4 + (lr0 + 0) * (DDIM / 4);
                const float4* x1 = xs4 + (lr0 + 1) * (DDIM / 4);
                const float4* x2 = xs4 + (lr0 + 2) * (DDIM / 4);
                const float4* x3 = xs4 + (lr0 + 3) * (DDIM / 4);

                float4 a0 = make_float4(0.f, 0.f, 0.f, 0.f);
                float4 a1 = a0, a2 = a0, a3 = a0;

                #pragma unroll 8
                for (int q = 0; q < DDIM / 4; q++) {
                    const float4 wv = w4[q];
                    float4 xv;
                    xv = x0[q];
                    a0.x = fmaf(xv.x, wv.x, a0.x); a0.y = fmaf(xv.y, wv.y, a0.y);
                    a0.z = fmaf(xv.z, wv.z, a0.z); a0.w = fmaf(xv.w, wv.w, a0.w);
                    xv = x1[q];
                    a1.x = fmaf(xv.x, wv.x, a1.x); a1.y = fmaf(xv.y, wv.y, a1.y);
                    a1.z = fmaf(xv.z, wv.z, a1.z); a1.w = fmaf(xv.w, wv.w, a1.w);
                    xv = x2[q];
                    a2.x = fmaf(xv.x, wv.x, a2.x); a2.y = fmaf(xv.y, wv.y, a2.y);
                    a2.z = fmaf(xv.z, wv.z, a2.z); a2.w = fmaf(xv.w, wv.w, a2.w);
                    xv = x3[q];
                    a3.x = fmaf(xv.x, wv.x, a3.x); a3.y = fmaf(xv.y, wv.y, a3.y);
                    a3.z = fmaf(xv.z, wv.z, a3.z); a3.w = fmaf(xv.w, wv.w, a3.w);
                }
                if (lane < KLAB) {
                    const int er = s * TS + lr0;      // row within e chunk
                    e_sm[(er + 0) * EPITCH + lane] = (a0.x + a0.y) + (a0.z + a0.w);
                    e_sm[(er + 1) * EPITCH + lane] = (a1.x + a1.y) + (a1.z + a1.w);
                    e_sm[(er + 2) * EPITCH + lane] = (a2.x + a2.y) + (a2.z + a2.w);
                    e_sm[(er + 3) * EPITCH + lane] = (a3.x + a3.y) + (a3.z + a3.w);
                }
            }
            __syncthreads();   // x_sm reused next tile
        }

        // ---- Phase 2: scan this chunk; scanning warp rotates per chunk ----
        if (warp == (c & 3)) {
            float Tcol[KLAB];
            #pragma unroll
            for (int j = 0; j < KLAB; j++) Tcol[j] = T[j * KLAB + yy];

            float l = (c == 0) ? 0.0f : carry_sm[lane];

            const int t_end = (c == NCHUNK - 1) ? CHUNK - 1 : CHUNK;
            for (int i = 0; i < t_end; i++) {
                const int t = c * CHUNK + i;
                const float* er = e_sm + i * EPITCH;
                float ev[EPITCH];
                #pragma unroll
                for (int q = 0; q < EPITCH / 4; q++)
                    *reinterpret_cast<float4*>(ev + 4 * q) =
                        reinterpret_cast<const float4*>(er)[q];

                // Faithful association (e + T) + l; two strict-'>' chains keep
                // first occurrence; cross-chain tie -> lower index.
                float l0 = __shfl_sync(0xffffffffu, l, 0);
                float m0 = (ev[0] + Tcol[0]) + l0; int a0 = 0;
                float l1 = __shfl_sync(0xffffffffu, l, 1);
                float m1 = (ev[1] + Tcol[1]) + l1; int a1 = 1;
                #pragma unroll
                for (int j = 2; j < KLAB; j++) {
                    float lj = __shfl_sync(0xffffffffu, l, j);
                    float s  = (ev[j] + Tcol[j]) + lj;
                    if ((j & 1) == 0) { if (s > m0) { m0 = s; a0 = j; } }
                    else              { if (s > m1) { m1 = s; a1 = j; } }
                }
                float m; int am;
                if (m1 > m0 || (m1 == m0 && a1 < a0)) { m = m1; am = a1; }
                else                                  { m = m0; am = a0; }

                if (lane < KLAB) bp_sm[t * KLAB + lane] = (unsigned char)am;
                l = m;
            }

            if (c == NCHUNK - 1) {
                // Final scores + warp argmax (tie -> lowest index).
                float fs = (lane < KLAB)
                               ? (e_sm[(CHUNK - 1) * EPITCH + lane] + l)
                               : -CUDART_INF_F;
                int idx = lane;
                #pragma unroll
                for (int off = 16; off > 0; off >>= 1) {
                    float ov = __shfl_down_sync(0xffffffffu, fs, off);
                    int   oi = __shfl_down_sync(0xffffffffu, idx, off);
                    if (ov > fs || (ov == fs && oi < idx)) { fs = ov; idx = oi; }
                }
                int y_last = __shfl_sync(0xffffffffu, idx, 0);

                // Backtrack (lane 0 of the scanning warp).
                if (lane == 0) {
                    int yv = y_last;
                    lab[LSEQ - 1] = (unsigned char)yv;
                    for (int t = LSEQ - 2; t >= 0; t--) {
                        yv = bp_sm[t * KLAB + yv];
                        lab[t] = (unsigned char)yv;
                    }
                }
            } else {
                carry_sm[lane] = l;   // hand carry to next chunk's scan warp
            }
        }
        __syncthreads();
    }

    // ---- Phase 3: coalesced store, labels as float values ----
    float* orow = out + (size_t)b * LSEQ;
    for (int i = tid; i < LSEQ; i += blockDim.x)
        orow[i] = (float)lab[i];
}

extern "C" void kernel_launch(void* const* d_in, const int* in_sizes, int n_in,
                              void* d_out, int out_size)
{
    // Rank-resolve inputs: X largest, T smallest, W the remaining one.
    int ix = 0, it = 0;
    for (int i = 1; i < n_in && i < 3; i++) {
        if (in_sizes[i] > in_sizes[ix]) ix = i;
        if (in_sizes[i] < in_sizes[it]) it = i;
    }
    int iw = 3 - ix - it;
    if (n_in < 3 || iw < 0 || iw > 2 || ix == it) { ix = 0; iw = 1; it = 2; }

    const float* X = (const float*)d_in[ix];
    const float* W = (const float*)d_in[iw];
    const float* T = (const float*)d_in[it];
    float* out = (float*)d_out;
    (void)out_size;

    crf_viterbi_kernel<<<BATCH, 128>>>(X, W, T, out);
}

// round 13
// speedup vs baseline: 1.8550x; 1.0394x over previous
#include <cuda_runtime.h>
#include <math_constants.h>

// CRF Viterbi decode, fused single kernel. Static smem 47.2 KB < 48 KB.
//   X: [4096, 512, 128] f32   W: [26, 128] f32   T: [26, 26] f32
//   out: [4096, 512] labels as FLOAT32 values (0.0 .. 25.0).
//
// R13 vs R12 (numerics bit-identical; rel_err canary 6.390682e-4):
//  - Phase-1 FMAs use PTX fma.rn.f32x2: packs (acc.x,acc.y) and (acc.z,acc.w)
//    pairs. Per-component IEEE FMA == scalar fmaf chain, half the issue slots.
//  - RBLK 4 -> 8 rows per warp iteration: W-LDS op count halves.
//  - TS 16 -> 32 staging rows, CHUNK 64 -> 32 (smem budget), NCHUNK 16.

#define LSEQ   512
#define KLAB   26
#define DDIM   128
#define EPITCH 28          // e row pitch in floats (112 B, 16B-aligned)
#define WPITCH 132         // W row pitch in floats (528 B, 16B-aligned)
#define CHUNK  32          // emission rows per scan chunk
#define NCHUNK (LSEQ / CHUNK)          // 16
#define TS     32          // X staging tile rows (== CHUNK, 1 tile per chunk)
#define RBLK   8           // rows per warp per tile (TS / 4 warps)
#define BATCH  4096

typedef unsigned long long u64;

// Packed dual FMA: d.lo = fma(a.lo,b.lo,d.lo), d.hi = fma(a.hi,b.hi,d.hi).
// Each half is a full-precision IEEE fp32 FMA -> bit-identical to two fmaf.
__device__ __forceinline__ void fma2(u64& d, u64 a, u64 b) {
    asm("fma.rn.f32x2 %0, %1, %2, %0;" : "+l"(d) : "l"(a), "l"(b));
}
__device__ __forceinline__ float lo_f(u64 v) {
    float f; unsigned r;
    asm("mov.b64 {%0, %1}, %2;" : "=r"(r), "=f"(f) : "l"(v));
    // NOTE: mov.b64 {lo, hi}: first output is LO. We want lo as float:
    return __uint_as_float(r);
}
__device__ __forceinline__ float hi_f(u64 v) {
    unsigned lo; float f;
    asm("mov.b64 {%0, %1}, %2;" : "=r"(lo), "=f"(f) : "l"(v));
    return f;
}

__global__ __launch_bounds__(128) void crf_viterbi_kernel(
    const float* __restrict__ X,
    const float* __restrict__ W,
    const float* __restrict__ T,
    float* __restrict__ out)
{
    __shared__ float e_sm[CHUNK * EPITCH];             //  3584 B
    __shared__ float w_sm[KLAB * WPITCH];              // 13728 B
    __shared__ float x_sm[TS * DDIM];                  // 16384 B
    __shared__ unsigned char bp_sm[(LSEQ - 1) * KLAB]; // 13286 B
    __shared__ unsigned char lab[LSEQ];                //   512 B
    __shared__ float carry_sm[32];                     //   128 B
                                                       // 47622 B total

    const int b    = blockIdx.x;
    const int tid  = threadIdx.x;
    const int warp = tid >> 5;
    const int lane = tid & 31;

    // ---- Stage W into smem ----
    for (int idx = tid; idx < KLAB * DDIM; idx += blockDim.x) {
        int k = idx >> 7;
        int d = idx & 127;
        w_sm[k * WPITCH + d] = W[idx];
    }
    __syncthreads();

    const int kk = lane < KLAB ? lane : 0;
    // W row as u64 pairs: pitch 132 floats = 66 u64 (row base 528 B, 16B-aligned)
    const ulonglong2* w2 = reinterpret_cast<const ulonglong2*>(w_sm + kk * WPITCH);
    const ulonglong2* xs2 = reinterpret_cast<const ulonglong2*>(x_sm);
    float4* xs4w = reinterpret_cast<float4*>(x_sm);
    const int yy = lane < KLAB ? lane : 0;

    for (int c = 0; c < NCHUNK; c++) {
        // ---- Phase 1: stage TS=32 rows coalesced, then compute emissions ----
        {
            const int row0 = c * CHUNK;
            const float4* xg = reinterpret_cast<const float4*>(
                X + ((size_t)b * LSEQ + row0) * DDIM);
            #pragma unroll
            for (int u = 0; u < (TS * DDIM / 4) / 128; u++)   // 8 per thread
                xs4w[tid + u * 128] = xg[tid + u * 128];
        }
        __syncthreads();

        {
            const int lr0 = warp * RBLK;   // local rows lr0 .. lr0+7
            // Accumulator pairs: aL[r] = (acc.x, acc.y), aH[r] = (acc.z, acc.w)
            u64 aL[RBLK], aH[RBLK];
            #pragma unroll
            for (int r = 0; r < RBLK; r++) { aL[r] = 0ull; aH[r] = 0ull; }

            #pragma unroll 4
            for (int q = 0; q < DDIM / 4; q++) {
                const ulonglong2 wv = w2[q];       // (w4q,w4q+1),(w4q+2,w4q+3)
                #pragma unroll
                for (int r = 0; r < RBLK; r++) {
                    const ulonglong2 xv = xs2[(lr0 + r) * (DDIM / 4) + q];
                    fma2(aL[r], xv.x, wv.x);       // k%4==0,1 partials
                    fma2(aH[r], xv.y, wv.y);       // k%4==2,3 partials
                }
            }
            if (lane < KLAB) {
                #pragma unroll
                for (int r = 0; r < RBLK; r++) {
                    // (acc.x + acc.y) + (acc.z + acc.w): identical combine.
                    float e = (lo_f(aL[r]) + hi_f(aL[r]))
                            + (lo_f(aH[r]) + hi_f(aH[r]));
                    e_sm[(lr0 + r) * EPITCH + lane] = e;
                }
            }
        }
        __syncthreads();

        // ---- Phase 2: scan this chunk; scanning warp rotates per chunk ----
        if (warp == (c & 3)) {
            float Tcol[KLAB];
            #pragma unroll
            for (int j = 0; j < KLAB; j++) Tcol[j] = T[j * KLAB + yy];

            float l = (c == 0) ? 0.0f : carry_sm[lane];

            const int t_end = (c == NCHUNK - 1) ? CHUNK - 1 : CHUNK;
            for (int i = 0; i < t_end; i++) {
                const int t = c * CHUNK + i;
                const float* er = e_sm + i * EPITCH;
                float ev[EPITCH];
                #pragma unroll
                for (int q = 0; q < EPITCH / 4; q++)
                    *reinterpret_cast<float4*>(ev + 4 * q) =
                        reinterpret_cast<const float4*>(er)[q];

                // Faithful association (e + T) + l; two strict-'>' chains keep
                // first occurrence; cross-chain tie -> lower index.
                float l0 = __shfl_sync(0xffffffffu, l, 0);
                float m0 = (ev[0] + Tcol[0]) + l0; int a0 = 0;
                float l1 = __shfl_sync(0xffffffffu, l, 1);
                float m1 = (ev[1] + Tcol[1]) + l1; int a1 = 1;
                #pragma unroll
                for (int j = 2; j < KLAB; j++) {
                    float lj = __shfl_sync(0xffffffffu, l, j);
                    float s  = (ev[j] + Tcol[j]) + lj;
                    if ((j & 1) == 0) { if (s > m0) { m0 = s; a0 = j; } }
                    else              { if (s > m1) { m1 = s; a1 = j; } }
                }
                float m; int am;
                if (m1 > m0 || (m1 == m0 && a1 < a0)) { m = m1; am = a1; }
                else                                  { m = m0; am = a0; }

                if (lane < KLAB) bp_sm[t * KLAB + lane] = (unsigned char)am;
                l = m;
            }

            if (c == NCHUNK - 1) {
                // Final scores + warp argmax (tie -> lowest index).
                float fs = (lane < KLAB)
                               ? (e_sm[(CHUNK - 1) * EPITCH + lane] + l)
                               : -CUDART_INF_F;
                int idx = lane;
                #pragma unroll
                for (int off = 16; off > 0; off >>= 1) {
                    float ov = __shfl_down_sync(0xffffffffu, fs, off);
                    int   oi = __shfl_down_sync(0xffffffffu, idx, off);
                    if (ov > fs || (ov == fs && oi < idx)) { fs = ov; idx = oi; }
                }
                int y_last = __shfl_sync(0xffffffffu, idx, 0);

                // Backtrack (lane 0 of the scanning warp).
                if (lane == 0) {
                    int yv = y_last;
                    lab[LSEQ - 1] = (unsigned char)yv;
                    for (int t = LSEQ - 2; t >= 0; t--) {
                        yv = bp_sm[t * KLAB + yv];
                        lab[t] = (unsigned char)yv;
                    }
                }
            } else {
                carry_sm[lane] = l;   // hand carry to next chunk's scan warp
            }
        }
        __syncthreads();
    }

    // ---- Phase 3: coalesced store, labels as float values ----
    float* orow = out + (size_t)b * LSEQ;
    for (int i = tid; i < LSEQ; i += blockDim.x)
        orow[i] = (float)lab[i];
}

extern "C" void kernel_launch(void* const* d_in, const int* in_sizes, int n_in,
                              void* d_out, int out_size)
{
    // Rank-resolve inputs: X largest, T smallest, W the remaining one.
    int ix = 0, it = 0;
    for (int i = 1; i < n_in && i < 3; i++) {
        if (in_sizes[i] > in_sizes[ix]) ix = i;
        if (in_sizes[i] < in_sizes[it]) it = i;
    }
    int iw = 3 - ix - it;
    if (n_in < 3 || iw < 0 || iw > 2 || ix == it) { ix = 0; iw = 1; it = 2; }

    const float* X = (const float*)d_in[ix];
    const float* W = (const float*)d_in[iw];
    const float* T = (const float*)d_in[it];
    float* out = (float*)d_out;
    (void)out_size;

    crf_viterbi_kernel<<<BATCH, 128>>>(X, W, T, out);
}

// round 14
// speedup vs baseline: 2.3016x; 1.2407x over previous
#include <cuda_runtime.h>
#include <math_constants.h>

// CRF Viterbi decode, fused, pipelined producer/consumer kernel.
//   X: [4096, 512, 128] f32   W: [26, 128] f32   T: [26, 26] f32
//   out: [4096, 512] labels as FLOAT32 values (0.0 .. 25.0).
//
// R14 vs R13 (numerics bit-identical; canary rel_err 6.390682e-4):
//  - 3 producer warps compute emission chunk i (double-buffered) WHILE the
//    consumer warp (rotating, i&3) scans chunk i-1. One syncthreads/iter.
//  - Scan value path: exact fmaxf TREE (max is associative) instead of
//    13-deep compare-select chains; argmax via descending eq-chain
//    (first occurrence, identical semantics).
//  - Scan adds packed via add.rn.f32x2 (each half IEEE-exact);
//    l-vector broadcast via smem (STS + 7 LDS.128) instead of 26 SHFL.

#define LSEQ   512
#define KLAB   26
#define DDIM   128
#define EPITCH 28          // e row pitch floats (112 B)
#define WPITCH 132         // W row pitch floats (528 B)
#define CHUNK  32
#define NCHUNK (LSEQ / CHUNK)   // 16
#define BATCH  4096

typedef unsigned long long u64;

union F2 { u64 u; float2 f; };

__device__ __forceinline__ F2 add2(F2 a, F2 b) {
    F2 r;
    asm("add.rn.f32x2 %0, %1, %2;" : "=l"(r.u) : "l"(a.u), "l"(b.u));
    return r;
}
__device__ __forceinline__ void fma2(u64& d, u64 a, u64 b) {
    asm("fma.rn.f32x2 %0, %1, %2, %0;" : "+l"(d) : "l"(a), "l"(b));
}
__device__ __forceinline__ float lo_f(u64 v) { F2 t; t.u = v; return t.f.x; }
__device__ __forceinline__ float hi_f(u64 v) { F2 t; t.u = v; return t.f.y; }

__global__ __launch_bounds__(128) void crf_viterbi_kernel(
    const float* __restrict__ X,
    const float* __restrict__ W,
    const float* __restrict__ T,
    float* __restrict__ out)
{
    __shared__ __align__(16) float w_sm[KLAB * WPITCH];     // 13728 B
    __shared__ __align__(16) float x_sm[3 * 4 * DDIM];      //  6144 B
    __shared__ __align__(16) float e_sm[2][CHUNK * EPITCH]; //  7168 B
    __shared__ __align__(16) float l_sm[EPITCH];            //   112 B
    __shared__ unsigned char bp_sm[(LSEQ - 1) * KLAB];      // 13286 B
    __shared__ unsigned char lab[LSEQ];                     //   512 B
                                                            // ~41 KB

    const int b    = blockIdx.x;
    const int tid  = threadIdx.x;
    const int warp = tid >> 5;
    const int lane = tid & 31;

    // ---- Stage W; zero l vector ----
    for (int idx = tid; idx < KLAB * DDIM; idx += blockDim.x) {
        int k = idx >> 7;
        int d = idx & 127;
        w_sm[k * WPITCH + d] = W[idx];
    }
    if (tid < EPITCH) l_sm[tid] = 0.0f;
    __syncthreads();

    const int kk = lane < KLAB ? lane : 0;
    const ulonglong2* w2 = reinterpret_cast<const ulonglong2*>(w_sm + kk * WPITCH);
    const int yy = kk;

    for (int i = 0; i <= NCHUNK; i++) {
        const int cw = i & 3;                 // consumer warp this iteration

        if (warp == cw) {
            // ================= CONSUMER: scan chunk i-1 =================
            if (i >= 1) {
                const int cc = i - 1;
                const float* eb = e_sm[cc & 1];

                // T column for this lane, packed in pairs (j, j+1).
                F2 T2[13];
                #pragma unroll
                for (int h = 0; h < 13; h++) {
                    T2[h].f.x = T[(2 * h)     * KLAB + yy];
                    T2[h].f.y = T[(2 * h + 1) * KLAB + yy];
                }

                float lcur = 0.0f;
                const int t_end = (cc == NCHUNK - 1) ? CHUNK - 1 : CHUNK;
                for (int s = 0; s < t_end; s++) {
                    const int t = cc * CHUNK + s;
                    const ulonglong2* er2 = reinterpret_cast<const ulonglong2*>(
                        eb + s * EPITCH);
                    const ulonglong2* lr2 = reinterpret_cast<const ulonglong2*>(l_sm);

                    // s_j = (e_j + T_jy) + l_j, packed pairs. Exact association.
                    F2 sv[13];
                    #pragma unroll
                    for (int h4 = 0; h4 < 7; h4++) {
                        const ulonglong2 e4 = er2[h4];
                        const ulonglong2 l4 = lr2[h4];
                        F2 ea, la, u;
                        ea.u = e4.x; la.u = l4.x;
                        u = add2(ea, T2[2 * h4]);
                        sv[2 * h4] = add2(u, la);
                        if (2 * h4 + 1 < 13) {
                            F2 ob, lb;
                            ob.u = e4.y; lb.u = l4.y;
                            u = add2(ob, T2[2 * h4 + 1]);
                            sv[2 * h4 + 1] = add2(u, lb);
                        }
                    }

                    // Exact max via fmaxf tree (max is associative).
                    float t13[13];
                    #pragma unroll
                    for (int h = 0; h < 13; h++)
                        t13[h] = fmaxf(sv[h].f.x, sv[h].f.y);
                    float r7[7];
                    #pragma unroll
                    for (int h = 0; h < 6; h++)
                        r7[h] = fmaxf(t13[2 * h], t13[2 * h + 1]);
                    r7[6] = t13[12];
                    float r4[4];
                    r4[0] = fmaxf(r7[0], r7[1]);
                    r4[1] = fmaxf(r7[2], r7[3]);
                    r4[2] = fmaxf(r7[4], r7[5]);
                    r4[3] = r7[6];
                    const float m = fmaxf(fmaxf(r4[0], r4[1]),
                                          fmaxf(r4[2], r4[3]));

                    // First-occurrence argmax: descending eq-chain
                    // (latency-tolerant, off the l->l critical path).
                    int am = 25;
                    #pragma unroll
                    for (int j = 24; j >= 0; j--) {
                        const float sj = (j & 1) ? sv[j >> 1].f.y : sv[j >> 1].f.x;
                        if (sj == m) am = j;
                    }
                    // j = 25 handled by init if it is the only max:
                    // (if s25==m and no smaller j matches, am stays 25 — correct;
                    //  if any smaller j matches, loop overwrote — correct.)

                    if (lane < KLAB) {
                        bp_sm[t * KLAB + lane] = (unsigned char)am;
                        l_sm[lane] = m;
                    }
                    lcur = m;
                    __syncwarp();
                }

                if (cc == NCHUNK - 1) {
                    // Final scores + warp argmax (tie -> lowest index).
                    float fs = (lane < KLAB)
                                   ? (eb[(CHUNK - 1) * EPITCH + lane] + lcur)
                                   : -CUDART_INF_F;
                    int idx = lane;
                    #pragma unroll
                    for (int off = 16; off > 0; off >>= 1) {
                        float ov = __shfl_down_sync(0xffffffffu, fs, off);
                        int   oi = __shfl_down_sync(0xffffffffu, idx, off);
                        if (ov > fs || (ov == fs && oi < idx)) { fs = ov; idx = oi; }
                    }
                    int y_last = __shfl_sync(0xffffffffu, idx, 0);

                    if (lane == 0) {
                        int yv = y_last;
                        lab[LSEQ - 1] = (unsigned char)yv;
                        for (int t = LSEQ - 2; t >= 0; t--) {
                            yv = bp_sm[t * KLAB + yv];
                            lab[t] = (unsigned char)yv;
                        }
                    }
                }
            }
        } else {
            // ================= PRODUCER: compute chunk i =================
            if (i < NCHUNK) {
                const int p = warp - (warp > cw ? 1 : 0);   // 0..2
                const int row0 = i * CHUNK;
                float* xs = x_sm + p * 4 * DDIM;
                float* eb = e_sm[i & 1];

                for (int blk = 0; blk < 3; blk++) {
                    __syncwarp();   // prior block's reads done before restage

                    // Stage 4 owned rows (r_loc = p + 3*idx), clamped tail.
                    #pragma unroll
                    for (int k = 0; k < 4; k++) {
                        const int idx  = blk * 4 + k;
                        const int rloc = p + 3 * idx;
                        const int rcl  = rloc < CHUNK ? rloc : CHUNK - 1;
                        const float4 v = reinterpret_cast<const float4*>(
                            X + ((size_t)b * LSEQ + row0 + rcl) * DDIM)[lane];
                        reinterpret_cast<float4*>(xs + k * DDIM)[lane] = v;
                    }
                    __syncwarp();

                    // Compute 4 rows; per-row accumulation order identical:
                    // float4 stride-4 partials over q ascending, (x+y)+(z+w).
                    u64 aL[4], aH[4];
                    #pragma unroll
                    for (int k = 0; k < 4; k++) { aL[k] = 0ull; aH[k] = 0ull; }

                    const ulonglong2* xr0 = reinterpret_cast<const ulonglong2*>(xs);
                    #pragma unroll 4
                    for (int q = 0; q < DDIM / 4; q++) {
                        const ulonglong2 wv = w2[q];
                        #pragma unroll
                        for (int k = 0; k < 4; k++) {
                            const ulonglong2 xv = xr0[k * (DDIM / 4) + q];
                            fma2(aL[k], xv.x, wv.x);
                            fma2(aH[k], xv.y, wv.y);
                        }
                    }
                    if (lane < KLAB) {
                        #pragma unroll
                        for (int k = 0; k < 4; k++) {
                            const int rloc = p + 3 * (blk * 4 + k);
                            if (rloc < CHUNK) {
                                const float e = (lo_f(aL[k]) + hi_f(aL[k]))
                                              + (lo_f(aH[k]) + hi_f(aH[k]));
                                eb[rloc * EPITCH + lane] = e;
                            }
                        }
                    }
                }
            }
        }
        __syncthreads();
    }

    // ---- coalesced store, labels as float values ----
    float* orow = out + (size_t)b * LSEQ;
    for (int ii = tid; ii < LSEQ; ii += blockDim.x)
        orow[ii] = (float)lab[ii];
}

extern "C" void kernel_launch(void* const* d_in, const int* in_sizes, int n_in,
                              void* d_out, int out_size)
{
    // Rank-resolve inputs: X largest, T smallest, W the remaining one.
    int ix = 0, it = 0;
    for (int i = 1; i < n_in && i < 3; i++) {
        if (in_sizes[i] > in_sizes[ix]) ix = i;
        if (in_sizes[i] < in_sizes[it]) it = i;
    }
    int iw = 3 - ix - it;
    if (n_in < 3 || iw < 0 || iw > 2 || ix == it) { ix = 0; iw = 1; it = 2; }

    const float* X = (const float*)d_in[ix];
    const float* W = (const float*)d_in[iw];
    const float* T = (const float*)d_in[it];
    float* out = (float*)d_out;
    (void)out_size;

    crf_viterbi_kernel<<<BATCH, 128>>>(X, W, T, out);
}

// round 15
// speedup vs baseline: 2.3360x; 1.0150x over previous
#include <cuda_runtime.h>
#include <math_constants.h>

// CRF Viterbi decode, SPLIT into two kernels via a device scratch buffer.
//   X: [4096, 512, 128] f32   W: [26, 128] f32   T: [26, 26] f32
//   out: [4096, 512] labels as FLOAT32 values (0.0 .. 25.0).
//
// Kernel A (emissions): e[b,t,k] = X[b,t,:].W[k,:] -> e_buf (pitch 28).
//   All 4 warps produce, 8-row register blocks, fma2 packed FMA chains
//   (per-row order: float4 stride-4 partials over q ascending, (x+y)+(z+w)).
// Kernel B (scan): one warp per word; software-pipelined uniform LDG of e
//   rows; add2 / fmaxf-tree / descending eq-chain step identical to R14.
// Numerics bit-identical to R14 (canary rel_err 6.390682e-4).

#define LSEQ   512
#define KLAB   26
#define DDIM   128
#define WPITCH 132
#define EPITCH 28          // e_buf row pitch floats (112 B, 16B-aligned)
#define BATCH  4096
#define WPB    2           // words per CTA in scan kernel

typedef unsigned long long u64;
union F2 { u64 u; float2 f; };

__device__ __forceinline__ F2 add2(F2 a, F2 b) {
    F2 r;
    asm("add.rn.f32x2 %0, %1, %2;" : "=l"(r.u) : "l"(a.u), "l"(b.u));
    return r;
}
__device__ __forceinline__ void fma2(u64& d, u64 a, u64 b) {
    asm("fma.rn.f32x2 %0, %1, %2, %0;" : "+l"(d) : "l"(a), "l"(b));
}
__device__ __forceinline__ float lo_f(u64 v) { F2 t; t.u = v; return t.f.x; }
__device__ __forceinline__ float hi_f(u64 v) { F2 t; t.u = v; return t.f.y; }

// Scratch: emissions, 4096 * 512 * 28 floats = 224 MiB (device global).
__device__ float e_buf[(size_t)BATCH * LSEQ * EPITCH];

// ============================ Kernel A: GEMM ============================
__global__ __launch_bounds__(128) void crf_emit_kernel(
    const float* __restrict__ X,
    const float* __restrict__ W)
{
    __shared__ __align__(16) float w_sm[KLAB * WPITCH];   // 13728 B
    __shared__ __align__(16) float x_sm[4][8 * DDIM];     // 16384 B

    const int b    = blockIdx.x;
    const int tid  = threadIdx.x;
    const int warp = tid >> 5;
    const int lane = tid & 31;

    for (int idx = tid; idx < KLAB * DDIM; idx += blockDim.x) {
        int k = idx >> 7;
        int d = idx & 127;
        w_sm[k * WPITCH + d] = W[idx];
    }
    __syncthreads();

    const int kk = lane < KLAB ? lane : 0;
    const ulonglong2* w2 = reinterpret_cast<const ulonglong2*>(w_sm + kk * WPITCH);
    float* xs = x_sm[warp];
    const ulonglong2* xs2 = reinterpret_cast<const ulonglong2*>(xs);

    // Warp handles rows [warp*128, warp*128+128), in 16 blocks of 8 rows.
    const int wrow0 = warp * 128;
    for (int blk = 0; blk < 16; blk++) {
        const int row0 = wrow0 + blk * 8;

        // Stage 8 rows coalesced (per-warp buffer; warp-local sync only).
        #pragma unroll
        for (int k = 0; k < 8; k++)
            reinterpret_cast<float4*>(xs + k * DDIM)[lane] =
                reinterpret_cast<const float4*>(
                    X + ((size_t)b * LSEQ + row0 + k) * DDIM)[lane];
        __syncwarp();

        u64 aL[8], aH[8];
        #pragma unroll
        for (int k = 0; k < 8; k++) { aL[k] = 0ull; aH[k] = 0ull; }

        #pragma unroll 4
        for (int q = 0; q < DDIM / 4; q++) {
            const ulonglong2 wv = w2[q];
            #pragma unroll
            for (int k = 0; k < 8; k++) {
                const ulonglong2 xv = xs2[k * (DDIM / 4) + q];
                fma2(aL[k], xv.x, wv.x);   // k%4 == 0,1 partials
                fma2(aH[k], xv.y, wv.y);   // k%4 == 2,3 partials
            }
        }
        if (lane < KLAB) {
            #pragma unroll
            for (int k = 0; k < 8; k++) {
                const float e = (lo_f(aL[k]) + hi_f(aL[k]))
                              + (lo_f(aH[k]) + hi_f(aH[k]));
                e_buf[((size_t)b * LSEQ + row0 + k) * EPITCH + lane] = e;
            }
        }
        __syncwarp();   // all reads of xs done before next stage
    }
}

// ============================ Kernel B: scan ============================
__global__ __launch_bounds__(64) void crf_scan_kernel(
    const float* __restrict__ T,
    float* __restrict__ out)
{
    __shared__ unsigned char bp_sm[WPB][(LSEQ - 1) * KLAB]; // 2 x 13286 B
    __shared__ __align__(16) float l_sm[WPB][32];
    __shared__ unsigned char lab[WPB][LSEQ];

    const int warp = threadIdx.x >> 5;     // 0..1 = word slot
    const int lane = threadIdx.x & 31;
    const int word = blockIdx.x * WPB + warp;
    const int yy   = lane < KLAB ? lane : 0;

    // T column pairs for this lane's label column.
    F2 T2[13];
    #pragma unroll
    for (int h = 0; h < 13; h++) {
        T2[h].f.x = T[(2 * h)     * KLAB + yy];
        T2[h].f.y = T[(2 * h + 1) * KLAB + yy];
    }

    l_sm[warp][lane] = 0.0f;
    __syncwarp();

    const float* erow = e_buf + (size_t)word * LSEQ * EPITCH;
    const ulonglong2* lr2 = reinterpret_cast<const ulonglong2*>(l_sm[warp]);

    // Preload e row 0 (uniform LDG.128 x7).
    ulonglong2 ev[7];
    {
        const ulonglong2* r0 = reinterpret_cast<const ulonglong2*>(erow);
        #pragma unroll
        for (int h = 0; h < 7; h++) ev[h] = r0[h];
    }

    float lcur = 0.0f;
    for (int t = 0; t < LSEQ - 1; t++) {
        // Software pipeline: issue next row's loads + L2 prefetch first.
        ulonglong2 nv[7];
        {
            const ulonglong2* rn = reinterpret_cast<const ulonglong2*>(
                erow + (size_t)(t + 1) * EPITCH);
            #pragma unroll
            for (int h = 0; h < 7; h++) nv[h] = rn[h];
            const int pt = (t + 16 < LSEQ) ? t + 16 : LSEQ - 1;
            asm volatile("prefetch.global.L2 [%0];"
                         :: "l"(erow + (size_t)pt * EPITCH));
        }

        // s_j = (e_j + T_jy) + l_j, packed pairs (exact association).
        F2 sv[13];
        #pragma unroll
        for (int h4 = 0; h4 < 7; h4++) {
            const ulonglong2 l4 = lr2[h4];
            F2 ea, la, u;
            ea.u = ev[h4].x; la.u = l4.x;
            u = add2(ea, T2[2 * h4]);
            sv[2 * h4] = add2(u, la);
            if (2 * h4 + 1 < 13) {
                F2 ob, lb;
                ob.u = ev[h4].y; lb.u = l4.y;
                u = add2(ob, T2[2 * h4 + 1]);
                sv[2 * h4 + 1] = add2(u, lb);
            }
        }

        // Exact max via fmaxf tree (max is associative).
        float t13[13];
        #pragma unroll
        for (int h = 0; h < 13; h++) t13[h] = fmaxf(sv[h].f.x, sv[h].f.y);
        float r7[7];
        #pragma unroll
        for (int h = 0; h < 6; h++) r7[h] = fmaxf(t13[2 * h], t13[2 * h + 1]);
        r7[6] = t13[12];
        float r4[4];
        r4[0] = fmaxf(r7[0], r7[1]);
        r4[1] = fmaxf(r7[2], r7[3]);
        r4[2] = fmaxf(r7[4], r7[5]);
        r4[3] = r7[6];
        const float m = fmaxf(fmaxf(r4[0], r4[1]), fmaxf(r4[2], r4[3]));

        // First-occurrence argmax: descending eq-chain.
        int am = 25;
        #pragma unroll
        for (int j = 24; j >= 0; j--) {
            const float sj = (j & 1) ? sv[j >> 1].f.y : sv[j >> 1].f.x;
            if (sj == m) am = j;
        }

        if (lane < KLAB) {
            bp_sm[warp][t * KLAB + lane] = (unsigned char)am;
            l_sm[warp][lane] = m;
        }
        lcur = m;

        #pragma unroll
        for (int h = 0; h < 7; h++) ev[h] = nv[h];
        __syncwarp();
    }

    // Final scores + warp argmax (tie -> lowest index).
    float fs = (lane < KLAB)
                   ? (erow[(size_t)(LSEQ - 1) * EPITCH + yy] + lcur)
                   : -CUDART_INF_F;
    int idx = lane;
    #pragma unroll
    for (int off = 16; off > 0; off >>= 1) {
        float ov = __shfl_down_sync(0xffffffffu, fs, off);
        int   oi = __shfl_down_sync(0xffffffffu, idx, off);
        if (ov > fs || (ov == fs && oi < idx)) { fs = ov; idx = oi; }
    }
    int y_last = __shfl_sync(0xffffffffu, idx, 0);

    if (lane == 0) {
        int yv = y_last;
        lab[warp][LSEQ - 1] = (unsigned char)yv;
        for (int t = LSEQ - 2; t >= 0; t--) {
            yv = bp_sm[warp][t * KLAB + yv];
            lab[warp][t] = (unsigned char)yv;
        }
    }
    __syncwarp();

    // Store this word's labels as float values (coalesced within warp).
    float* orow = out + (size_t)word * LSEQ;
    for (int i = lane; i < LSEQ; i += 32)
        orow[i] = (float)lab[warp][i];
}

extern "C" void kernel_launch(void* const* d_in, const int* in_sizes, int n_in,
                              void* d_out, int out_size)
{
    // Rank-resolve inputs: X largest, T smallest, W the remaining one.
    int ix = 0, it = 0;
    for (int i = 1; i < n_in && i < 3; i++) {
        if (in_sizes[i] > in_sizes[ix]) ix = i;
        if (in_sizes[i] < in_sizes[it]) it = i;
    }
    int iw = 3 - ix - it;
    if (n_in < 3 || iw < 0 || iw > 2 || ix == it) { ix = 0; iw = 1; it = 2; }

    const float* X = (const float*)d_in[ix];
    const float* W = (const float*)d_in[iw];
    const float* T = (const float*)d_in[it];
    float* out = (float*)d_out;
    (void)out_size;

    crf_emit_kernel<<<BATCH, 128>>>(X, W);
    crf_scan_kernel<<<BATCH / WPB, 32 * WPB>>>(T, out);
}